// round 17
// baseline (speedup 1.0000x reference)
#include <cuda_runtime.h>
#include <cuda_bf16.h>
#include <math.h>
#include <stdint.h>

#define NBATCH 8
#define TSEQ   2048
#define CDIM   128
#define SCL    0.08838834764831845f   // 1/sqrt(128)
#define NEGMAX -3.402823466e38f

// -------- scratch (static __device__ per harness rules) --------
__device__ float         g_Qf [(size_t)NBATCH * TSEQ * CDIM]; // fp32 Q (raw)
__device__ float         g_Kf [(size_t)NBATCH * TSEQ * CDIM]; // fp32 K (raw)
__device__ __nv_bfloat16 g_Qb [(size_t)NBATCH * TSEQ * CDIM]; // bf16 Q (pre-scaled)
__device__ __nv_bfloat16 g_Kb [(size_t)NBATCH * TSEQ * CDIM]; // bf16 K
__device__ __nv_bfloat16 g_Wos[128 * 256];                    // Wo split [hi||lo]

__device__ __forceinline__ uint32_t s2u(const void* p) {
    uint32_t a;
    asm("{ .reg .u64 t; cvta.to.shared.u64 t, %1; cvt.u32.u64 %0, t; }" : "=r"(a) : "l"(p));
    return a;
}
__device__ __forceinline__ uint32_t umx(uint32_t a, uint32_t b) { return a > b ? a : b; }
__device__ __forceinline__ uint32_t umn(uint32_t a, uint32_t b) { return a < b ? a : b; }

__device__ __forceinline__ void mma_bf16(float& c0, float& c1, float& c2, float& c3,
    uint32_t a0, uint32_t a1, uint32_t a2, uint32_t a3, uint32_t b0, uint32_t b1) {
    asm volatile("mma.sync.aligned.m16n8k16.row.col.f32.bf16.bf16.f32 "
        "{%0,%1,%2,%3}, {%4,%5,%6,%7}, {%8,%9}, {%0,%1,%2,%3};"
        : "+f"(c0), "+f"(c1), "+f"(c2), "+f"(c3)
        : "r"(a0), "r"(a1), "r"(a2), "r"(a3), "r"(b0), "r"(b1));
}
#define LDMX4(d, ad) \
    asm volatile("ldmatrix.sync.aligned.m8n8.x4.shared.b16 {%0,%1,%2,%3}, [%4];" \
        : "=r"((d)[0]), "=r"((d)[1]), "=r"((d)[2]), "=r"((d)[3]) : "r"(ad))

#define CPA16(dst32, gptr) \
    asm volatile("cp.async.ca.shared.global [%0], [%1], 16;" :: "r"(dst32), "l"(gptr) : "memory")

// inverse of the order-preserving packed map, rounded DOWN (safe threshold)
__device__ __forceinline__ float unpack_th(uint32_t v) {
    uint32_t b = ((int)v < 0) ? ((v & 0xFFFFF800u) ^ 0x80000000u)
                              : (~v | 0x7FFu);
    return __uint_as_float(b);
}

// float-gated packed top-4 insert (common path: 1 compare + rare branch)
#define GINS4(r0, r1, r2, r3, th, f, cc) { \
    float _f = (f); \
    if (_f > (th)) { \
        uint32_t mb = __float_as_uint(_f); \
        mb = ((int)mb < 0) ? ~mb : (mb | 0x80000000u); \
        uint32_t x = (mb & 0xFFFFF800u) | (cc); \
        uint32_t tt; \
        tt = umx(r0, x); x = umn(r0, x); r0 = tt; \
        tt = umx(r1, x); x = umn(r1, x); r1 = tt; \
        tt = umx(r2, x); x = umn(r2, x); r2 = tt; \
        r3 = umx(r3, x); \
        th = unpack_th(r3); \
    } }

#define INS6A(u, xx) { uint32_t y = (xx), tt; \
    tt = umx((u)[0], y); y = umn((u)[0], y); (u)[0] = tt; \
    tt = umx((u)[1], y); y = umn((u)[1], y); (u)[1] = tt; \
    tt = umx((u)[2], y); y = umn((u)[2], y); (u)[2] = tt; \
    tt = umx((u)[3], y); y = umn((u)[3], y); (u)[3] = tt; \
    tt = umx((u)[4], y); y = umn((u)[4], y); (u)[4] = tt; \
    (u)[5] = umx((u)[5], y); }

#define INS3(vv, cc) do { float _v = (vv); int _c = (cc); \
    if (_v > b2) { \
        if (_v > b1) { \
            if (_v > b0) { b2 = b1; i2 = i1; b1 = b0; i1 = i0; b0 = _v; i0 = _c; } \
            else         { b2 = b1; i2 = i1; b1 = _v; i1 = _c; } \
        } else           { b2 = _v; i2 = _c; } \
    } } while (0)

__device__ __forceinline__ void quad_merge6(uint32_t u[6]) {
    #pragma unroll
    for (int mk = 1; mk <= 2; mk <<= 1) {
        uint32_t o[6];
        #pragma unroll
        for (int j = 0; j < 6; j++) o[j] = __shfl_xor_sync(0xffffffffu, u[j], mk);
        #pragma unroll
        for (int j = 0; j < 6; j++) { INS6A(u, o[j]); }
    }
}
__device__ __forceinline__ void merge6_smem(uint32_t u[6], const uint32_t* p) {
    #pragma unroll
    for (int j = 0; j < 6; j++) { uint32_t x = p[j]; INS6A(u, x); }
}
__device__ __forceinline__ void store6(uint32_t* p, const uint32_t u[6]) {
    #pragma unroll
    for (int j = 0; j < 6; j++) p[j] = u[j];
}

// ============================================================================
// Q/K projection (SIMT fp32, exact) + attention zero-fill + Wo-split prep.
// ============================================================================
__global__ __launch_bounds__(256) void proj_split(
    const float* __restrict__ E, const float* __restrict__ Wq, const float* __restrict__ Wk,
    float* __restrict__ attn, const float4* __restrict__ Wo)
{
    extern __shared__ float smf[];
    float* As = smf;
    float* Bs = smf + 128 * 128;
    const int tid = threadIdx.x, tx = tid & 15, ty = tid >> 4;
    const int m0 = blockIdx.x * 128;
    const int isK = blockIdx.y;
    const float* W = isK ? Wk : Wq;
    float*         df = isK ? g_Kf : g_Qf;
    __nv_bfloat16* db = isK ? g_Kb : g_Qb;
    const float bscale = isK ? 1.f : SCL;

    if (isK == 0 && blockIdx.x < 16) {
        int local = blockIdx.x * 256 + tid;
        float4 v = Wo[local];
        int row = local >> 5, c4b = (local & 31) * 4;
        __nv_bfloat16 h0 = __float2bfloat16_rn(v.x), h1 = __float2bfloat16_rn(v.y);
        __nv_bfloat16 h2 = __float2bfloat16_rn(v.z), h3 = __float2bfloat16_rn(v.w);
        __nv_bfloat162 hp0, hp1, lp0, lp1;
        hp0.x = h0; hp0.y = h1; hp1.x = h2; hp1.y = h3;
        lp0.x = __float2bfloat16_rn(v.x - __bfloat162float(h0));
        lp0.y = __float2bfloat16_rn(v.y - __bfloat162float(h1));
        lp1.x = __float2bfloat16_rn(v.z - __bfloat162float(h2));
        lp1.y = __float2bfloat16_rn(v.w - __bfloat162float(h3));
        __nv_bfloat162* ph = (__nv_bfloat162*)(g_Wos + (size_t)row * 256 + c4b);
        ph[0] = hp0; ph[1] = hp1;
        __nv_bfloat162* pl = (__nv_bfloat162*)(g_Wos + (size_t)row * 256 + 128 + c4b);
        pl[0] = lp0; pl[1] = lp1;
    }

    {
        const float4* src = (const float4*)(E + (size_t)m0 * 128);
        #pragma unroll
        for (int i = tid; i < 128 * 32; i += 256) {
            int r = i & 127, cq = i >> 7;
            float4 v = src[(size_t)r * 32 + cq];
            float* d = As + (cq * 4) * 128 + r;
            d[0] = v.x; d[128] = v.y; d[256] = v.z; d[384] = v.w;
        }
        const float4* srcb = (const float4*)W;
        #pragma unroll
        for (int i = tid; i < 128 * 32; i += 256) {
            int r = i & 127, cq = i >> 7;
            float4 v = srcb[(size_t)r * 32 + cq];
            float* d = Bs + (cq * 4) * 128 + r;
            d[0] = v.x; d[128] = v.y; d[256] = v.z; d[384] = v.w;
        }
    }

    {
        const int cid = blockIdx.y * 128 + blockIdx.x;
        uint4* az = (uint4*)attn + (size_t)cid * 32768 + tid;
        uint4 zz = make_uint4(0, 0, 0, 0);
        #pragma unroll 8
        for (int j = 0; j < 128; j++) az[j * 256] = zz;
    }
    __syncthreads();

    float acc[8][8];
    #pragma unroll
    for (int i = 0; i < 8; i++)
        #pragma unroll
        for (int j = 0; j < 8; j++) acc[i][j] = 0.f;

    #pragma unroll 4
    for (int c = 0; c < 128; c++) {
        const float* ac = As + c * 128;
        const float* bc = Bs + c * 128;
        float4 a0 = *(const float4*)(ac + ty * 4);
        float4 a1 = *(const float4*)(ac + 64 + ty * 4);
        float4 b0 = *(const float4*)(bc + tx * 4);
        float4 b1 = *(const float4*)(bc + 64 + tx * 4);
        float a[8] = {a0.x, a0.y, a0.z, a0.w, a1.x, a1.y, a1.z, a1.w};
        float b[8] = {b0.x, b0.y, b0.z, b0.w, b1.x, b1.y, b1.z, b1.w};
        #pragma unroll
        for (int i = 0; i < 8; i++)
            #pragma unroll
            for (int j = 0; j < 8; j++)
                acc[i][j] += a[i] * b[j];
    }

    #pragma unroll
    for (int ih = 0; ih < 2; ih++) {
        #pragma unroll
        for (int i = 0; i < 4; i++) {
            const int row = m0 + ih * 64 + ty * 4 + i;
            #pragma unroll
            for (int jh = 0; jh < 2; jh++) {
                const int col = jh * 64 + tx * 4;
                float a0 = acc[ih * 4 + i][jh * 4 + 0];
                float a1 = acc[ih * 4 + i][jh * 4 + 1];
                float a2 = acc[ih * 4 + i][jh * 4 + 2];
                float a3 = acc[ih * 4 + i][jh * 4 + 3];
                *(float4*)(df + (size_t)row * 128 + col) = make_float4(a0, a1, a2, a3);
                __nv_bfloat162 p01, p23;
                p01.x = __float2bfloat16_rn(a0 * bscale);
                p01.y = __float2bfloat16_rn(a1 * bscale);
                p23.x = __float2bfloat16_rn(a2 * bscale);
                p23.y = __float2bfloat16_rn(a3 * bscale);
                __nv_bfloat162* pb = (__nv_bfloat162*)(db + (size_t)row * 128 + col);
                pb[0] = p01; pb[1] = p23;
            }
        }
    }
}

// ============================================================================
// Exact rescore of 6 candidates for one row (quad-cooperative), top-3+softmax.
// ============================================================================
__device__ __forceinline__ void rescore_row(
    const uint32_t* u6, int n, int row, int c4, int* sidx3, float* swgt3)
{
    const float4* qp = (const float4*)(g_Qf + ((size_t)n * TSEQ + row) * 128) + c4 * 8;
    float4 qv[8];
    #pragma unroll
    for (int p = 0; p < 8; p++) qv[p] = qp[p];
    int ids[6];
    #pragma unroll
    for (int j = 0; j < 6; j++) ids[j] = (int)(u6[j] & 2047u);
    float sc[6];
    #pragma unroll
    for (int j = 0; j < 6; j++) {
        const float4* kp = (const float4*)(g_Kf + ((size_t)n * TSEQ + ids[j]) * 128) + c4 * 8;
        float s = 0.f;
        #pragma unroll
        for (int p = 0; p < 8; p++) {
            float4 kv = kp[p];
            s += qv[p].x * kv.x + qv[p].y * kv.y + qv[p].z * kv.z + qv[p].w * kv.w;
        }
        s += __shfl_xor_sync(0xffffffffu, s, 1);
        s += __shfl_xor_sync(0xffffffffu, s, 2);
        sc[j] = s * SCL;
    }
    float b0 = -INFINITY, b1 = -INFINITY, b2 = -INFINITY;
    int i0 = 0, i1 = 0, i2 = 0;
    #pragma unroll
    for (int j = 0; j < 6; j++) INS3(sc[j], ids[j]);
    if (c4 == 0) {
        float e1 = expf(b1 - b0), e2 = expf(b2 - b0);
        float inv = 1.f / (1.f + e1 + e2);
        sidx3[0] = i0; sidx3[1] = i1; sidx3[2] = i2;
        swgt3[0] = inv; swgt3[1] = e1 * inv; swgt3[2] = e2 * inv;
    }
}

// ============================================================================
// Fused scores + top-k + attn@V + output projection.
// 32x32 warp tiles: wq = row group (32 rows via 2 A tiles), wc = col group
// (32 cols). B fragments feed 2 A tiles -> smem B-read bytes halved.
// cp.async K staging; float-gated top-4 chains.
// ============================================================================
#define OFQ   0u
#define OFK0  34816u
#define OFK1  69632u
#define OFOA  0u
#define OFWO  69632u
#define OFU6A 137216
#define OFU6B (137216 + 3072)
#define OFSI  (137216 + 6144)
#define OFSW  (137216 + 6144 + 1536)
#define SMEMS (137216 + 6144 + 1536 + 1536)   // 146432

__global__ __launch_bounds__(512) void scores_fused(
    const float* __restrict__ E, float* __restrict__ attn,
    const float* __restrict__ bo, float* __restrict__ out)
{
    extern __shared__ __align__(16) char smc[];
    const uint32_t sb = s2u(smc);
    const int tid = threadIdx.x, lane = tid & 31, wid = tid >> 5;
    const int g = lane >> 2, c4 = lane & 3;
    const int wq = wid & 3, wc = wid >> 2;   // row group / col group
    const int n = blockIdx.y, m0 = blockIdx.x * 128;
    uint32_t* u6a  = (uint32_t*)(smc + OFU6A);
    uint32_t* u6b  = (uint32_t*)(smc + OFU6B);
    int*      sidx = (int*)(smc + OFSI);
    float*    swgt = (float*)(smc + OFSW);

    // ---- load Q tile + K tile 0 ----
    {
        const uint4* gq = (const uint4*)(g_Qb + ((size_t)n * TSEQ + m0) * 128);
        const uint4* gk = (const uint4*)(g_Kb + ((size_t)n * TSEQ) * 128);
        #pragma unroll
        for (int j = 0; j < 4; j++) {
            int i = tid + j * 512;
            int r = i >> 4, c = i & 15;
            *(uint4*)(smc + OFQ  + r * 272 + c * 16) = gq[i];
            *(uint4*)(smc + OFK0 + r * 272 + c * 16) = gk[i];
        }
    }
    __syncthreads();

    // A fragments: 2 tiles (rows wq*32.. and wq*32+16..), 8 k-steps each
    uint32_t A0[8][4], A1[8][4];
    {
        uint32_t ab = sb + OFQ + (uint32_t)((wq * 32 + (lane & 15)) * 272 + (lane >> 4) * 16);
        #pragma unroll
        for (int ks = 0; ks < 8; ks++) LDMX4(A0[ks], ab + ks * 32);
        #pragma unroll
        for (int ks = 0; ks < 8; ks++) LDMX4(A1[ks], ab + 16 * 272 + ks * 32);
    }

    // 4 gated top-4 chains: rows g, g+8, g+16, g+24 (within warp's 32 rows)
    uint32_t qA0 = 0x00800000u, qA1 = 0x00800000u, qA2 = 0x00800000u, qA3 = 0x00800000u;
    uint32_t qB0 = 0x00800000u, qB1 = 0x00800000u, qB2 = 0x00800000u, qB3 = 0x00800000u;
    uint32_t qC0 = 0x00800000u, qC1 = 0x00800000u, qC2 = 0x00800000u, qC3 = 0x00800000u;
    uint32_t qD0 = 0x00800000u, qD1 = 0x00800000u, qD2 = 0x00800000u, qD3 = 0x00800000u;
    float thA = NEGMAX, thB = NEGMAX, thC = NEGMAX, thD = NEGMAX;

    #pragma unroll 1
    for (int t = 0; t < 16; t++) {
        const uint32_t bufR = (t & 1) ? OFK1 : OFK0;
        const uint32_t bufW = (t & 1) ? OFK0 : OFK1;

        // stage next K tile via cp.async (no registers, latency hidden by MMAs)
        if (t < 15) {
            const char* gk = (const char*)(g_Kb + ((size_t)n * TSEQ + (size_t)(t + 1) * 128) * 128);
            #pragma unroll
            for (int j = 0; j < 4; j++) {
                int i = tid + j * 512;
                int r = i >> 4, c = i & 15;
                CPA16(sb + bufW + (uint32_t)(r * 272 + c * 16), gk + (size_t)i * 16);
            }
            asm volatile("cp.async.commit_group;" ::: "memory");
        }

        // MMAs: 2 nt-pairs, each with 4 independent chains (2 nt x 2 A tiles)
        #pragma unroll
        for (int p = 0; p < 2; p++) {
            const int ntg = wc * 4 + p * 2;
            float ac[4][4];
            #pragma unroll
            for (int j = 0; j < 4; j++)
                #pragma unroll
                for (int q = 0; q < 4; q++) ac[j][q] = 0.f;

            const char* br0 = smc + bufR + (ntg * 8 + g) * 272 + c4 * 4;
            const char* br1 = br0 + 8 * 272;
            #pragma unroll
            for (int ks = 0; ks < 8; ks++) {
                uint32_t b00 = *(const uint32_t*)(br0 + ks * 32);
                uint32_t b01 = *(const uint32_t*)(br0 + ks * 32 + 16);
                uint32_t b10 = *(const uint32_t*)(br1 + ks * 32);
                uint32_t b11 = *(const uint32_t*)(br1 + ks * 32 + 16);
                mma_bf16(ac[0][0], ac[0][1], ac[0][2], ac[0][3],
                         A0[ks][0], A0[ks][1], A0[ks][2], A0[ks][3], b00, b01);
                mma_bf16(ac[1][0], ac[1][1], ac[1][2], ac[1][3],
                         A1[ks][0], A1[ks][1], A1[ks][2], A1[ks][3], b00, b01);
                mma_bf16(ac[2][0], ac[2][1], ac[2][2], ac[2][3],
                         A0[ks][0], A0[ks][1], A0[ks][2], A0[ks][3], b10, b11);
                mma_bf16(ac[3][0], ac[3][1], ac[3][2], ac[3][3],
                         A1[ks][0], A1[ks][1], A1[ks][2], A1[ks][3], b10, b11);
            }

            const uint32_t col = (uint32_t)(t * 128 + ntg * 8 + 2 * c4);
            // row g       : ac[0][0,1] (nt0), ac[2][0,1] (nt1)
            GINS4(qA0, qA1, qA2, qA3, thA, ac[0][0], col);
            GINS4(qA0, qA1, qA2, qA3, thA, ac[0][1], col + 1);
            GINS4(qA0, qA1, qA2, qA3, thA, ac[2][0], col + 8);
            GINS4(qA0, qA1, qA2, qA3, thA, ac[2][1], col + 9);
            // row g+8     : ac[0][2,3], ac[2][2,3]
            GINS4(qB0, qB1, qB2, qB3, thB, ac[0][2], col);
            GINS4(qB0, qB1, qB2, qB3, thB, ac[0][3], col + 1);
            GINS4(qB0, qB1, qB2, qB3, thB, ac[2][2], col + 8);
            GINS4(qB0, qB1, qB2, qB3, thB, ac[2][3], col + 9);
            // row g+16    : ac[1][0,1], ac[3][0,1]
            GINS4(qC0, qC1, qC2, qC3, thC, ac[1][0], col);
            GINS4(qC0, qC1, qC2, qC3, thC, ac[1][1], col + 1);
            GINS4(qC0, qC1, qC2, qC3, thC, ac[3][0], col + 8);
            GINS4(qC0, qC1, qC2, qC3, thC, ac[3][1], col + 9);
            // row g+24    : ac[1][2,3], ac[3][2,3]
            GINS4(qD0, qD1, qD2, qD3, thD, ac[1][2], col);
            GINS4(qD0, qD1, qD2, qD3, thD, ac[1][3], col + 1);
            GINS4(qD0, qD1, qD2, qD3, thD, ac[3][2], col + 8);
            GINS4(qD0, qD1, qD2, qD3, thD, ac[3][3], col + 9);
        }

        if (t < 15) asm volatile("cp.async.wait_group 0;" ::: "memory");
        __syncthreads();
    }

    // ---- quad merge (cols within this warp's 32-col group) ----
    uint32_t UA[6] = {qA0, qA1, qA2, qA3, 0, 0};
    uint32_t UB[6] = {qB0, qB1, qB2, qB3, 0, 0};
    uint32_t UC[6] = {qC0, qC1, qC2, qC3, 0, 0};
    uint32_t UD[6] = {qD0, qD1, qD2, qD3, 0, 0};
    quad_merge6(UA); quad_merge6(UB); quad_merge6(UC); quad_merge6(UD);

    const int r0 = wq * 32 + g;   // rows r0, r0+8, r0+16, r0+24
    // ---- cross col-group merge: (1->0, 3->2) then (2->0) ----
    if (c4 == 0) {
        if (wc == 1) { store6(u6a + r0 * 6, UA); store6(u6a + (r0 + 8) * 6, UB);
                       store6(u6a + (r0 + 16) * 6, UC); store6(u6a + (r0 + 24) * 6, UD); }
        if (wc == 3) { store6(u6b + r0 * 6, UA); store6(u6b + (r0 + 8) * 6, UB);
                       store6(u6b + (r0 + 16) * 6, UC); store6(u6b + (r0 + 24) * 6, UD); }
    }
    __syncthreads();
    if (wc == 0) { merge6_smem(UA, u6a + r0 * 6); merge6_smem(UB, u6a + (r0 + 8) * 6);
                   merge6_smem(UC, u6a + (r0 + 16) * 6); merge6_smem(UD, u6a + (r0 + 24) * 6); }
    if (wc == 2) { merge6_smem(UA, u6b + r0 * 6); merge6_smem(UB, u6b + (r0 + 8) * 6);
                   merge6_smem(UC, u6b + (r0 + 16) * 6); merge6_smem(UD, u6b + (r0 + 24) * 6); }
    __syncthreads();
    if (wc == 2 && c4 == 0) {
        store6(u6a + r0 * 6, UA); store6(u6a + (r0 + 8) * 6, UB);
        store6(u6a + (r0 + 16) * 6, UC); store6(u6a + (r0 + 24) * 6, UD);
    }
    __syncthreads();
    if (wc == 0) {
        merge6_smem(UA, u6a + r0 * 6); merge6_smem(UB, u6a + (r0 + 8) * 6);
        merge6_smem(UC, u6a + (r0 + 16) * 6); merge6_smem(UD, u6a + (r0 + 24) * 6);
        if (c4 == 0) {
            store6(u6a + r0 * 6, UA); store6(u6a + (r0 + 8) * 6, UB);
            store6(u6a + (r0 + 16) * 6, UC); store6(u6a + (r0 + 24) * 6, UD);
        }
    }
    __syncthreads();

    // ---- load Wo split into smem (K buffers dead now) + exact rescore ----
    {
        const uint4* gw = (const uint4*)g_Wos;
        #pragma unroll
        for (int j = 0; j < 8; j++) {
            int i = tid + j * 512;
            int r = i >> 5, c = i & 31;
            *(uint4*)(smc + OFWO + r * 528 + c * 16) = gw[i];
        }
    }
    {
        const int row = wid * 8 + g;
        uint32_t cand[6];
        #pragma unroll
        for (int j = 0; j < 6; j++) cand[j] = u6a[row * 6 + j];
        rescore_row(cand, n, m0 + row, c4, sidx + row * 3, swgt + row * 3);
    }
    __syncthreads();

    // scatter the 3 weights per row (zeros already written by proj_split)
    if (tid < 128) {
        float* arow = attn + ((size_t)n * TSEQ + m0 + tid) * TSEQ;
        arow[sidx[tid * 3 + 0]] = swgt[tid * 3 + 0];
        arow[sidx[tid * 3 + 1]] = swgt[tid * 3 + 1];
        arow[sidx[tid * 3 + 2]] = swgt[tid * 3 + 2];
    }

    // attn @ V (V = raw E) -> split-bf16 OA rows in SMEM (528-stride)
    for (int rr = wid; rr < 128; rr += 16) {
        int j0 = sidx[rr * 3], j1 = sidx[rr * 3 + 1], j2 = sidx[rr * 3 + 2];
        float w0 = swgt[rr * 3], w1 = swgt[rr * 3 + 1], w2 = swgt[rr * 3 + 2];
        float4 p0 = ((const float4*)(E + ((size_t)n * TSEQ + j0) * 128))[lane];
        float4 p1 = ((const float4*)(E + ((size_t)n * TSEQ + j1) * 128))[lane];
        float4 p2 = ((const float4*)(E + ((size_t)n * TSEQ + j2) * 128))[lane];
        float ox = w0 * p0.x + w1 * p1.x + w2 * p2.x;
        float oy = w0 * p0.y + w1 * p1.y + w2 * p2.y;
        float oz = w0 * p0.z + w1 * p1.z + w2 * p2.z;
        float ow = w0 * p0.w + w1 * p1.w + w2 * p2.w;
        __nv_bfloat16 hx = __float2bfloat16_rn(ox), hy = __float2bfloat16_rn(oy);
        __nv_bfloat16 hz = __float2bfloat16_rn(oz), hw = __float2bfloat16_rn(ow);
        __nv_bfloat162 h01, h23, l01, l23;
        h01.x = hx; h01.y = hy; h23.x = hz; h23.y = hw;
        l01.x = __float2bfloat16_rn(ox - __bfloat162float(hx));
        l01.y = __float2bfloat16_rn(oy - __bfloat162float(hy));
        l23.x = __float2bfloat16_rn(oz - __bfloat162float(hz));
        l23.y = __float2bfloat16_rn(ow - __bfloat162float(hw));
        char* orow = smc + OFOA + rr * 528;
        *(__nv_bfloat162*)(orow + lane * 8)       = h01;
        *(__nv_bfloat162*)(orow + lane * 8 + 4)   = h23;
        *(__nv_bfloat162*)(orow + 256 + lane * 8)     = l01;
        *(__nv_bfloat162*)(orow + 256 + lane * 8 + 4) = l23;
    }
    __syncthreads();

    // ---- fused output projection: out_tile = OA @ Wo^T + bo ----
    {
        const int wg = wid & 7, hf = wid >> 3;   // row-group / nt-half
        uint32_t Ag[16][4];
        uint32_t ab2 = sb + OFOA + (uint32_t)((wg * 16 + (lane & 15)) * 528 + (lane >> 4) * 16);
        #pragma unroll
        for (int ks = 0; ks < 16; ks++) LDMX4(Ag[ks], ab2 + ks * 32);

        #pragma unroll
        for (int ntg = 0; ntg < 2; ntg++) {
            float acc[4][4];
            #pragma unroll
            for (int j = 0; j < 4; j++)
                #pragma unroll
                for (int q = 0; q < 4; q++) acc[j][q] = 0.f;

            #pragma unroll
            for (int ks = 0; ks < 8; ks++) {
                #pragma unroll
                for (int j = 0; j < 4; j++) {
                    const char* br = smc + OFWO + ((hf * 8 + ntg * 4 + j) * 8 + g) * 528 + c4 * 4;
                    uint32_t b0 = *(const uint32_t*)(br + ks * 32);
                    uint32_t b1 = *(const uint32_t*)(br + ks * 32 + 16);
                    mma_bf16(acc[j][0], acc[j][1], acc[j][2], acc[j][3],
                             Ag[ks][0], Ag[ks][1], Ag[ks][2], Ag[ks][3], b0, b1);
                    mma_bf16(acc[j][0], acc[j][1], acc[j][2], acc[j][3],
                             Ag[8 + ks][0], Ag[8 + ks][1], Ag[8 + ks][2], Ag[8 + ks][3], b0, b1);
                    uint32_t l0 = *(const uint32_t*)(br + 256 + ks * 32);
                    uint32_t l1 = *(const uint32_t*)(br + 256 + ks * 32 + 16);
                    mma_bf16(acc[j][0], acc[j][1], acc[j][2], acc[j][3],
                             Ag[ks][0], Ag[ks][1], Ag[ks][2], Ag[ks][3], l0, l1);
                }
            }

            #pragma unroll
            for (int j = 0; j < 4; j++) {
                const int nt = hf * 8 + ntg * 4 + j;
                const int rA = n * TSEQ + m0 + wg * 16 + g;
                const int col = nt * 8 + 2 * c4;
                float bb0 = bo[col], bb1 = bo[col + 1];
                *(float2*)(out + (size_t)rA * 128 + col)       = make_float2(acc[j][0] + bb0, acc[j][1] + bb1);
                *(float2*)(out + (size_t)(rA + 8) * 128 + col) = make_float2(acc[j][2] + bb0, acc[j][3] + bb1);
            }
        }
    }
}

// ============================================================================
extern "C" void kernel_launch(void* const* d_in, const int* in_sizes, int n_in,
                              void* d_out, int out_size)
{
    const float* E  = (const float*)d_in[0];
    const float* Wq = (const float*)d_in[2];
    const float* Wk = (const float*)d_in[3];
    const float* Wo = (const float*)d_in[4];
    const float* bo = (const float*)d_in[5];

    float* out  = (float*)d_out;                       // [8,2048,128]
    float* attn = out + (size_t)NBATCH * TSEQ * CDIM;  // [8,1,2048,2048]

    const int SMEM_G = 128 * 128 * 2 * sizeof(float);  // 131072 (proj)
    cudaFuncSetAttribute(proj_split,   cudaFuncAttributeMaxDynamicSharedMemorySize, SMEM_G);
    cudaFuncSetAttribute(scores_fused, cudaFuncAttributeMaxDynamicSharedMemorySize, SMEMS);

    proj_split<<<dim3(128, 2), 256, SMEM_G>>>(E, Wq, Wk, attn, (const float4*)Wo);
    scores_fused<<<dim3(16, NBATCH), 512, SMEMS>>>(E, attn, bo, out);
}